// round 16
// baseline (speedup 1.0000x reference)
#include <cuda_runtime.h>
#include <cuda_fp16.h>
#include <float.h>
#include <math.h>
#include <stdint.h>

// Problem constants
#define B_    8
#define NPTS  8192
#define NS    2048
#define D1    128
#define D2    256
#define C1    384      // D1 + D2
#define C2    256
#define C3    128
#define MTOT  (B_ * NPTS)   // 65536
#define GRIDX (MTOT / 128)  // 512 column blocks per GEMM

// ---------------------------------------------------------------------------
// Scratch (static device globals — no allocations allowed)
// ---------------------------------------------------------------------------
__device__ __align__(16) uint32_t g_BP1[(size_t)(C1 / 2) * MTOT]; // 48 MB GEMM1 B (packed fp16 k-pairs)
__device__ __align__(16) uint32_t g_BP2[(size_t)(C2 / 2) * MTOT]; // 32 MB h1 RAW packed fp16 k-pairs
__device__ float  g_h2[(size_t)C3 * MTOT];       // 32 MB GEMM2 out (pre-BN) [c][m]
__device__ float  g_sfT[(size_t)B_ * NS * D2];   // 16 MB sfeat transposed [b][s][c]
__device__ float4 g_w[MTOT];                     // per-point 3-NN weights
__device__ int4   g_i[MTOT];                     // per-point 3-NN indices
__device__ float2 g_ss1[C2];                     // BN1 (scale, shift) fp32
__device__ float2 g_ss2[C3];                     // BN2 (scale, shift)
__device__ __align__(4) __half g_sc1h[C2];       // BN1 scale, fp16 (fragment fuse)
__device__ __align__(4) __half g_sh1h[C2];       // BN1 shift, fp16
__device__ __align__(16) __half g_W1h[C2 * C1];  // fp16 weights, row-major
__device__ __align__(16) __half g_W2h[C3 * C2];
// per-block BN partials (deterministic reduction, no atomics)
__device__ float g_psA[C2 * GRIDX], g_pqA[C2 * GRIDX];
__device__ float g_psB[C3 * GRIDX], g_pqB[C3 * GRIDX];

__device__ __forceinline__ void mma16816(float* d, const uint32_t* a, const uint32_t* b) {
    asm volatile(
        "mma.sync.aligned.m16n8k16.row.col.f32.f16.f16.f32 "
        "{%0,%1,%2,%3}, {%4,%5,%6,%7}, {%8,%9}, {%0,%1,%2,%3};\n"
        : "+f"(d[0]), "+f"(d[1]), "+f"(d[2]), "+f"(d[3])
        : "r"(a[0]), "r"(a[1]), "r"(a[2]), "r"(a[3]), "r"(b[0]), "r"(b[1]));
}

__device__ __forceinline__ void cp_async16(uint32_t smem_addr, const void* gptr) {
    asm volatile("cp.async.ca.shared.global [%0], [%1], 16;\n"
                 :: "r"(smem_addr), "l"(gptr));
}
#define CP_COMMIT()  asm volatile("cp.async.commit_group;\n")
#define CP_WAIT(N)   asm volatile("cp.async.wait_group %0;\n" :: "n"(N))

// ---------------------------------------------------------------------------
// Kernel 1a (launch #1): weights -> fp16
// ---------------------------------------------------------------------------
__global__ void __launch_bounds__(256) prep_w_kernel(
    const float* __restrict__ W1, const float* __restrict__ W2)
{
    int i = blockIdx.x * 256 + threadIdx.x;
    if (i < C2 * C1) g_W1h[i] = __float2half_rn(W1[i]);
    if (i < C3 * C2) g_W2h[i] = __float2half_rn(W2[i]);
}

// ---------------------------------------------------------------------------
// Kernel 1b (launch #2): pack skip -> g_BP1 rows 0..63 (half2 k-pairs)
// ---------------------------------------------------------------------------
__global__ void __launch_bounds__(256) prep_skip_kernel(
    const float* __restrict__ skip)
{
    int pb = blockIdx.x;
    int cp = pb >> 6;
    int m0 = ((pb & 63) * 256 + threadIdx.x) * 4;
    int b  = m0 / NPTS;
    int n  = m0 % NPTS;
    const float* r0 = skip + ((size_t)b * D1 + 2 * cp)     * NPTS + n;
    const float* r1 = skip + ((size_t)b * D1 + 2 * cp + 1) * NPTS + n;
    float4 v0 = *(const float4*)r0;
    float4 v1 = *(const float4*)r1;
    uint32_t p[4];
    const float* x0 = &v0.x; const float* x1 = &v1.x;
    #pragma unroll
    for (int e = 0; e < 4; e++) {
        __half2 h = __floats2half2_rn(x0[e], x1[e]);
        p[e] = *reinterpret_cast<uint32_t*>(&h);
    }
    *(uint4*)&g_BP1[(size_t)cp * MTOT + m0] = *(uint4*)p;
}

// ---------------------------------------------------------------------------
// Kernel 1c (launch #3): transpose sfeat [b][c][s] -> g_sfT [b][s][c]
// ---------------------------------------------------------------------------
__global__ void __launch_bounds__(256) prep_tr_kernel(
    const float* __restrict__ sfeat)
{
    __shared__ float tile[32][33];
    int tb = blockIdx.x;
    int s0 = (tb & 63) * 32;
    int c0 = ((tb >> 6) & 7) * 32;
    int b  = tb >> 9;
    int tx = threadIdx.x & 31;
    int ty = threadIdx.x >> 5;

    #pragma unroll
    for (int r = 0; r < 32; r += 8)
        tile[ty + r][tx] = sfeat[((size_t)b * D2 + c0 + ty + r) * NS + s0 + tx];
    __syncthreads();
    #pragma unroll
    for (int r = 0; r < 32; r += 8)
        g_sfT[((size_t)b * NS + s0 + ty + r) * D2 + c0 + tx] = tile[tx][ty + r];
}

// ---------------------------------------------------------------------------
// Kernel 2 (launch #4 — PROFILED THIS ROUND): 3-NN search.
//   Proven config: 2 pts/thread, 256 blocks x 128 threads. Byte-identical.
// ---------------------------------------------------------------------------
__global__ void __launch_bounds__(128) knn_kernel(
    const float* __restrict__ pp, const float* __restrict__ spp)
{
    __shared__ float4 ssmp[NS];

    const int b   = blockIdx.x >> 5;
    const int n0  = (blockIdx.x & 31) << 8;
    const int tid = threadIdx.x;

    const float* sb = spp + (size_t)b * 3 * NS;
    for (int s = tid; s < NS; s += 128) {
        float x = sb[s], y = sb[s + NS], z = sb[s + 2 * NS];
        ssmp[s] = make_float4(x, y, z, fmaf(x, x, fmaf(y, y, z * z)));
    }
    __syncthreads();

    const int nA = n0 + tid, nB = nA + 128;
    const float* pb = pp + (size_t)b * 3 * NPTS;
    const float ax = pb[nA], ay = pb[nA + NPTS], az = pb[nA + 2 * NPTS];
    const float bx = pb[nB], by = pb[nB + NPTS], bz = pb[nB + 2 * NPTS];

    float ad0 = FLT_MAX, ad1 = FLT_MAX, ad2 = FLT_MAX;
    float bd0 = FLT_MAX, bd1 = FLT_MAX, bd2 = FLT_MAX;
    int   ai0 = 0, ai1 = 0, ai2 = 0, bi0 = 0, bi1 = 0, bi2 = 0;

    #pragma unroll 4
    for (int j = 0; j < NS; j++) {
        float4 q  = ssmp[j];
        float sA = fmaf(-2.0f, fmaf(ax, q.x, fmaf(ay, q.y, az * q.z)), q.w);
        float sB = fmaf(-2.0f, fmaf(bx, q.x, fmaf(by, q.y, bz * q.z)), q.w);
        if (sA < ad2) {
            if (sA < ad1) {
                ad2 = ad1; ai2 = ai1;
                if (sA < ad0) { ad1 = ad0; ai1 = ai0; ad0 = sA; ai0 = j; }
                else          { ad1 = sA; ai1 = j; }
            } else { ad2 = sA; ai2 = j; }
        }
        if (sB < bd2) {
            if (sB < bd1) {
                bd2 = bd1; bi2 = bi1;
                if (sB < bd0) { bd1 = bd0; bi1 = bi0; bd0 = sB; bi0 = j; }
                else          { bd1 = sB; bi1 = j; }
            } else { bd2 = sB; bi2 = j; }
        }
    }

    {
        const float p2 = fmaf(ax, ax, fmaf(ay, ay, az * az));
        float a0 = 1.0f / ((ad0 + p2) + 1e-8f);
        float a1 = 1.0f / ((ad1 + p2) + 1e-8f);
        float a2 = 1.0f / ((ad2 + p2) + 1e-8f);
        float inv = 1.0f / (a0 + a1 + a2);
        g_w[b * NPTS + nA] = make_float4(a0 * inv, a1 * inv, a2 * inv, 0.0f);
        g_i[b * NPTS + nA] = make_int4(ai0, ai1, ai2, 0);
    }
    {
        const float p2 = fmaf(bx, bx, fmaf(by, by, bz * bz));
        float a0 = 1.0f / ((bd0 + p2) + 1e-8f);
        float a1 = 1.0f / ((bd1 + p2) + 1e-8f);
        float a2 = 1.0f / ((bd2 + p2) + 1e-8f);
        float inv = 1.0f / (a0 + a1 + a2);
        g_w[b * NPTS + nB] = make_float4(a0 * inv, a1 * inv, a2 * inv, 0.0f);
        g_i[b * NPTS + nB] = make_int4(bi0, bi1, bi2, 0);
    }
}

// ---------------------------------------------------------------------------
// Kernel 3 (launch #5): interpolation -> g_BP1 rows 64..191 (half2 packed)
// ---------------------------------------------------------------------------
__global__ void __launch_bounds__(256) interp_kernel()
{
    __shared__ float  st[D2][33];
    __shared__ float4 sw[32];
    __shared__ int4   si[32];

    const int m0  = blockIdx.x * 32;
    const int b   = m0 / NPTS;
    const int tid = threadIdx.x;

    if (tid < 32) { sw[tid] = g_w[m0 + tid]; si[tid] = g_i[m0 + tid]; }
    __syncthreads();

    const float* fT = g_sfT + (size_t)b * NS * D2;
    #pragma unroll 8
    for (int p = 0; p < 32; p++) {
        float4 w = sw[p];
        int4   ii = si[p];
        float v = fmaf(w.x, __ldg(fT + (size_t)ii.x * D2 + tid),
                  fmaf(w.y, __ldg(fT + (size_t)ii.y * D2 + tid),
                       w.z * __ldg(fT + (size_t)ii.z * D2 + tid)));
        st[tid][p] = v;
    }
    __syncthreads();

    const int cpb = tid >> 3;
    const int j   = (tid & 7) << 2;
    #pragma unroll
    for (int r = 0; r < 4; r++) {
        int cp = r * 32 + cpb;
        uint32_t v[4];
        #pragma unroll
        for (int e = 0; e < 4; e++) {
            __half2 h = __floats2half2_rn(st[2 * cp][j + e], st[2 * cp + 1][j + e]);
            v[e] = *reinterpret_cast<uint32_t*>(&h);
        }
        *(uint4*)&g_BP1[(size_t)(64 + cp) * MTOT + m0 + j] = *(uint4*)v;
    }
}

// ---------------------------------------------------------------------------
// Shared MMA compute (As [m][kpair], Bs [kpair][n ^ (kp<<3)])
// ---------------------------------------------------------------------------
#define MMA_COMPUTE(ASBUF, BSBUF)                                             \
{                                                                             \
    uint32_t bf[4][2];                                                        \
    _Pragma("unroll")                                                         \
    for (int nt = 0; nt < 4; nt++) {                                          \
        int n = wn * 32 + nt * 8 + g;                                         \
        bf[nt][0] = (BSBUF)[t * 128 + (n ^ (t << 3))];                        \
        bf[nt][1] = (BSBUF)[(t + 4) * 128 + (n ^ ((t + 4) << 3))];            \
    }                                                                         \
    _Pragma("unroll")                                                         \
    for (int mt = 0; mt < 4; mt++) {                                          \
        int r = wm * 64 + mt * 16 + g;                                        \
        uint32_t ah[4];                                                       \
        ah[0] = (ASBUF)[r * 8 + t];                                           \
        ah[1] = (ASBUF)[(r + 8) * 8 + t];                                     \
        ah[2] = (ASBUF)[r * 8 + t + 4];                                       \
        ah[3] = (ASBUF)[(r + 8) * 8 + t + 4];                                 \
        _Pragma("unroll")                                                     \
        for (int nt = 0; nt < 4; nt++)                                        \
            mma16816(acc[mt][nt], ah, bf[nt]);                                \
    }                                                                         \
}

// gemm2 variant: BN1 + ReLU applied on B fragments (half2 hfma2/hmax2)
#define MMA_COMPUTE_BN(ASBUF, BSBUF, KI)                                      \
{                                                                             \
    const __half2 z2 = __float2half2_rn(0.0f);                                \
    __half2 sc0 = ((const __half2*)g_sc1h)[(KI) * 8 + t];                     \
    __half2 sh0 = ((const __half2*)g_sh1h)[(KI) * 8 + t];                     \
    __half2 sc1 = ((const __half2*)g_sc1h)[(KI) * 8 + t + 4];                 \
    __half2 sh1 = ((const __half2*)g_sh1h)[(KI) * 8 + t + 4];                 \
    uint32_t bf[4][2];                                                        \
    _Pragma("unroll")                                                         \
    for (int nt = 0; nt < 4; nt++) {                                          \
        int n = wn * 32 + nt * 8 + g;                                         \
        bf[nt][0] = (BSBUF)[t * 128 + (n ^ (t << 3))];                        \
        bf[nt][1] = (BSBUF)[(t + 4) * 128 + (n ^ ((t + 4) << 3))];            \
        __half2 h0 = *reinterpret_cast<__half2*>(&bf[nt][0]);                 \
        __half2 h1 = *reinterpret_cast<__half2*>(&bf[nt][1]);                 \
        h0 = __hmax2(__hfma2(h0, sc0, sh0), z2);                              \
        h1 = __hmax2(__hfma2(h1, sc1, sh1), z2);                              \
        bf[nt][0] = *reinterpret_cast<uint32_t*>(&h0);                        \
        bf[nt][1] = *reinterpret_cast<uint32_t*>(&h1);                        \
    }                                                                         \
    _Pragma("unroll")                                                         \
    for (int mt = 0; mt < 4; mt++) {                                          \
        int r = wm * 64 + mt * 16 + g;                                        \
        uint32_t ah[4];                                                       \
        ah[0] = (ASBUF)[r * 8 + t];                                           \
        ah[1] = (ASBUF)[(r + 8) * 8 + t];                                     \
        ah[2] = (ASBUF)[r * 8 + t + 4];                                       \
        ah[3] = (ASBUF)[(r + 8) * 8 + t + 4];                                 \
        _Pragma("unroll")                                                     \
        for (int nt = 0; nt < 4; nt++)                                        \
            mma16816(acc[mt][nt], ah, bf[nt]);                                \
    }                                                                         \
}

// BN partial-stat emission (sum/sumsq from fp32 accumulators)
#define BN_PARTIALS(PSUM, PSQ, SS_SMEM, SQ_SMEM)                              \
{                                                                             \
    __syncthreads();                                                          \
    float* Ssum = (SS_SMEM);                                                  \
    float* Ssq  = (SQ_SMEM);                                                  \
    const int ci = wn * 4 + t;                                                \
    _Pragma("unroll")                                                         \
    for (int mt = 0; mt < 4; mt++) {                                          \
        int r0 = wm * 64 + mt * 16 + g;                                       \
        float s0 = 0.f, q0 = 0.f, s1 = 0.f, q1 = 0.f;                         \
        _Pragma("unroll")                                                     \
        for (int nt = 0; nt < 4; nt++) {                                      \
            float e0 = acc[mt][nt][0], e1 = acc[mt][nt][1];                   \
            float e2 = acc[mt][nt][2], e3 = acc[mt][nt][3];                   \
            s0 += e0 + e1;  q0 += e0 * e0 + e1 * e1;                          \
            s1 += e2 + e3;  q1 += e2 * e2 + e3 * e3;                          \
        }                                                                     \
        Ssum[ci * 128 + r0]     = s0;  Ssq[ci * 128 + r0]     = q0;           \
        Ssum[ci * 128 + r0 + 8] = s1;  Ssq[ci * 128 + r0 + 8] = q1;           \
    }                                                                         \
    __syncthreads();                                                          \
    if (tid < 128) {                                                          \
        float s = 0.f;                                                        \
        _Pragma("unroll")                                                     \
        for (int c = 0; c < 16; c++) s += Ssum[c * 128 + tid];                \
        (PSUM)[(size_t)(i0 + tid) * GRIDX + blockIdx.x] = s;                  \
    } else {                                                                  \
        int r = tid - 128;                                                    \
        float q = 0.f;                                                        \
        _Pragma("unroll")                                                     \
        for (int c = 0; c < 16; c++) q += Ssq[c * 128 + r];                   \
        (PSQ)[(size_t)(i0 + r) * GRIDX + blockIdx.x] = q;                     \
    }                                                                         \
}

// ---------------------------------------------------------------------------
// Kernel 4 (launch #6): GEMM1 — unchanged (measured 70us stable).
//   Epilogue packs h1 as raw fp16 k-pairs into g_BP2 + BN1 partials.
// ---------------------------------------------------------------------------
__global__ void __launch_bounds__(256) gemm1_kernel()
{
    __shared__ uint32_t As[4][128 * 8];
    __shared__ uint32_t Bs[4][8 * 128];

    const int tid  = threadIdx.x;
    const int lane = tid & 31;
    const int wid  = tid >> 5;
    const int wm   = wid >> 2;
    const int wn   = wid & 3;
    const int g    = lane >> 2;
    const int t    = lane & 3;

    const int j0 = blockIdx.x * 128;
    const int i0 = blockIdx.y * 128;

    const int arow = tid >> 1;
    const int akh  = tid & 1;
    const int brp  = tid >> 5;
    const int bc0  = lane * 4;

    const uint32_t a_dst0 = (uint32_t)__cvta_generic_to_shared(&As[0][arow * 8 + akh * 4]);
    const uint32_t b_dst0 = (uint32_t)__cvta_generic_to_shared(&Bs[0][brp * 128 + (bc0 ^ (brp << 3))]);
    const __half*   a_src0 = g_W1h + (size_t)(i0 + arow) * C1 + akh * 8;
    const uint32_t* b_src0 = g_BP1 + (size_t)brp * MTOT + j0 + bc0;

    float acc[4][4][4];
    #pragma unroll
    for (int mt = 0; mt < 4; mt++)
        #pragma unroll
        for (int nt = 0; nt < 4; nt++)
            #pragma unroll
            for (int e = 0; e < 4; e++) acc[mt][nt][e] = 0.0f;

    #define G1_ISSUE(step)                                                    \
    {                                                                         \
        int s_ = (step) & 3;                                                  \
        cp_async16(a_dst0 + s_ * 4096, a_src0 + (step) * 16);                 \
        cp_async16(b_dst0 + s_ * 4096, b_src0 + (size_t)(step) * 8 * MTOT);   \
        CP_COMMIT();                                                          \
    }

    G1_ISSUE(0); G1_ISSUE(1); G1_ISSUE(2);

    #pragma unroll 1
    for (int i = 0; i < 21; i++) {
        CP_WAIT(2);
        __syncthreads();
        G1_ISSUE(i + 3);
        MMA_COMPUTE(As[i & 3], Bs[i & 3]);
    }
    CP_WAIT(2); __syncthreads(); MMA_COMPUTE(As[21 & 3], Bs[21 & 3]);
    CP_WAIT(1); __syncthreads(); MMA_COMPUTE(As[22 & 3], Bs[22 & 3]);
    CP_WAIT(0); __syncthreads(); MMA_COMPUTE(As[23 & 3], Bs[23 & 3]);

    // ---- epilogue: pack h1 -> raw fp16 k-pairs in g_BP2 ----
    #pragma unroll
    for (int mt = 0; mt < 4; mt++) {
        #pragma unroll
        for (int nt = 0; nt < 4; nt++) {
            float v0 = acc[mt][nt][0], v1 = acc[mt][nt][1];
            float v2 = acc[mt][nt][2], v3 = acc[mt][nt][3];
            float p0 = __shfl_down_sync(0xFFFFFFFFu, v0, 4);
            float p1 = __shfl_down_sync(0xFFFFFFFFu, v1, 4);
            float p2 = __shfl_down_sync(0xFFFFFFFFu, v2, 4);
            float p3 = __shfl_down_sync(0xFFFFFFFFu, v3, 4);
            if (!(g & 1)) {
                int r   = wm * 64 + mt * 16 + g;
                int cp0 = (i0 + r) >> 1;
                int col = j0 + wn * 32 + nt * 8 + 2 * t;
                __half2 h0 = __floats2half2_rn(v0, p0);
                __half2 h1 = __floats2half2_rn(v1, p1);
                uint2 w0 = make_uint2(*(uint32_t*)&h0, *(uint32_t*)&h1);
                *(uint2*)&g_BP2[(size_t)cp0 * MTOT + col] = w0;
                __half2 h2 = __floats2half2_rn(v2, p2);
                __half2 h3 = __floats2half2_rn(v3, p3);
                uint2 w1 = make_uint2(*(uint32_t*)&h2, *(uint32_t*)&h3);
                *(uint2*)&g_BP2[(size_t)(cp0 + 4) * MTOT + col] = w1;
            }
        }
    }

    BN_PARTIALS(g_psA, g_pqA, (float*)As, (float*)Bs);
    #undef G1_ISSUE
}

// ---------------------------------------------------------------------------
// Kernel 5: GEMM2 — pure-copy cp.async loaders; BN1+ReLU fused on B FRAGMENTS.
// ---------------------------------------------------------------------------
__global__ void __launch_bounds__(256) gemm2_kernel()
{
    __shared__ uint32_t As[4][128 * 8];
    __shared__ uint32_t Bs[4][8 * 128];

    const int tid  = threadIdx.x;
    const int lane = tid & 31;
    const int wid  = tid >> 5;
    const int wm   = wid >> 2;
    const int wn   = wid & 3;
    const int g    = lane >> 2;
    const int t    = lane & 3;

    const int j0 = blockIdx.x * 128;
    const int i0 = 0;

    const int arow = tid >> 1;
    const int akh  = tid & 1;
    const int brp  = tid >> 5;
    const int bc0  = lane * 4;

    const uint32_t a_dst0 = (uint32_t)__cvta_generic_to_shared(&As[0][arow * 8 + akh * 4]);
    const uint32_t b_dst0 = (uint32_t)__cvta_generic_to_shared(&Bs[0][brp * 128 + (bc0 ^ (brp << 3))]);
    const __half*   a_src0 = g_W2h + (size_t)arow * C2 + akh * 8;
    const uint32_t* b_src0 = g_BP2 + (size_t)brp * MTOT + j0 + bc0;

    float acc[4][4][4];
    #pragma unroll
    for (int mt = 0; mt < 4; mt++)
        #pragma unroll
        for (int nt = 0; nt < 4; nt++)
            #pragma unroll
            for (int e = 0; e < 4; e++) acc[mt][nt][e] = 0.0f;

    #define G2_ISSUE(step)                                                    \
    {                                                                         \
        int s_ = (step) & 3;                                                  \
        cp_async16(a_dst0 + s_ * 4096, a_src0 + (step) * 16);                 \
        cp_async16(b_dst0 + s_ * 4096, b_src0 + (size_t)(step) * 8 * MTOT);   \
        CP_COMMIT();                                                          \
    }

    G2_ISSUE(0); G2_ISSUE(1); G2_ISSUE(2);

    #pragma unroll 1
    for (int i = 0; i < 13; i++) {
        CP_WAIT(2);
        __syncthreads();
        G2_ISSUE(i + 3);
        MMA_COMPUTE_BN(As[i & 3], Bs[i & 3], i);
    }
    CP_WAIT(2); __syncthreads(); MMA_COMPUTE_BN(As[13 & 3], Bs[13 & 3], 13);
    CP_WAIT(1); __syncthreads(); MMA_COMPUTE_BN(As[14 & 3], Bs[14 & 3], 14);
    CP_WAIT(0); __syncthreads(); MMA_COMPUTE_BN(As[15 & 3], Bs[15 & 3], 15);

    // store h2 fp32 + BN2 partials
    #pragma unroll
    for (int mt = 0; mt < 4; mt++) {
        #pragma unroll
        for (int nt = 0; nt < 4; nt++) {
            int row = wm * 64 + mt * 16 + g;
            int col = j0 + wn * 32 + nt * 8 + 2 * t;
            *(float2*)&g_h2[(size_t)row * MTOT + col] =
                make_float2(acc[mt][nt][0], acc[mt][nt][1]);
            *(float2*)&g_h2[(size_t)(row + 8) * MTOT + col] =
                make_float2(acc[mt][nt][2], acc[mt][nt][3]);
        }
    }

    BN_PARTIALS(g_psB, g_pqB, (float*)As, (float*)Bs);
    #undef G2_ISSUE
}

// ---------------------------------------------------------------------------
// Kernel 6: reduce per-block partials -> per-channel (scale, shift)
// ---------------------------------------------------------------------------
__global__ void __launch_bounds__(256) bn_reduce_kernel(
    const float* __restrict__ g, const float* __restrict__ beta, int which)
{
    const int c   = blockIdx.x;
    const int tid = threadIdx.x;
    const float* ps = (which == 1) ? g_psA : g_psB;
    const float* pq = (which == 1) ? g_pqA : g_pqB;

    double s = (double)ps[(size_t)c * GRIDX + tid] + (double)ps[(size_t)c * GRIDX + tid + 256];
    double q = (double)pq[(size_t)c * GRIDX + tid] + (double)pq[(size_t)c * GRIDX + tid + 256];

    __shared__ double r1[256], r2[256];
    r1[tid] = s;  r2[tid] = q;
    __syncthreads();
    for (int o = 128; o > 0; o >>= 1) {
        if (tid < o) { r1[tid] += r1[tid + o]; r2[tid] += r2[tid + o]; }
        __syncthreads();
    }
    if (tid == 0) {
        double mean = r1[0] / (double)MTOT;
        double var  = r2[0] / (double)MTOT - mean * mean;
        double rs   = 1.0 / sqrt(var + 1e-5);
        float scale = (float)((double)g[c] * rs);
        float shift = (float)((double)beta[c] - mean * (double)g[c] * rs);
        if (which == 1) {
            g_ss1[c]  = make_float2(scale, shift);
            g_sc1h[c] = __float2half_rn(scale);
            g_sh1h[c] = __float2half_rn(shift);
        } else {
            g_ss2[c] = make_float2(scale, shift);
        }
    }
}

// ---------------------------------------------------------------------------
// Kernel 7: final BN2 + ReLU + layout transform [c][b*N+n] -> [b][c][n]
// ---------------------------------------------------------------------------
__global__ void __launch_bounds__(256) bn_out_kernel(float* __restrict__ out)
{
    size_t f = (size_t)blockIdx.x * blockDim.x + threadIdx.x;
    size_t e = f * 4;
    int c = (int)(e / MTOT);
    int m = (int)(e % MTOT);
    int b = m / NPTS;
    int n = m % NPTS;

    float4 v = ((const float4*)g_h2)[f];
    float2 ss = g_ss2[c];
    v.x = fmaxf(fmaf(v.x, ss.x, ss.y), 0.0f);
    v.y = fmaxf(fmaf(v.y, ss.x, ss.y), 0.0f);
    v.z = fmaxf(fmaf(v.z, ss.x, ss.y), 0.0f);
    v.w = fmaxf(fmaf(v.w, ss.x, ss.y), 0.0f);
    *(float4*)(out + ((size_t)b * C3 + c) * NPTS + n) = v;
}

// ---------------------------------------------------------------------------
// Launcher — prep split into 3 launches so KNN lands in the profiled #4 slot
// ---------------------------------------------------------------------------
extern "C" void kernel_launch(void* const* d_in, const int* in_sizes, int n_in,
                              void* d_out, int out_size)
{
    const float* pp    = (const float*)d_in[0];
    const float* spp   = (const float*)d_in[1];
    const float* skip  = (const float*)d_in[2];
    const float* sfeat = (const float*)d_in[3];
    const float* W1    = (const float*)d_in[4];
    // d_in[5] = b1 (cancels inside BN)
    const float* g1    = (const float*)d_in[6];
    const float* be1   = (const float*)d_in[7];
    const float* W2    = (const float*)d_in[8];
    // d_in[9] = b2 (cancels inside BN)
    const float* g2    = (const float*)d_in[10];
    const float* be2   = (const float*)d_in[11];
    float* out = (float*)d_out;

    // #1..#3: preprocessing (split; work identical to the fused version)
    prep_w_kernel<<<384, 256>>>(W1, W2);
    prep_skip_kernel<<<4096, 256>>>(skip);
    prep_tr_kernel<<<4096, 256>>>(sfeat);

    // #4 (PROFILED): 3-NN
    knn_kernel<<<B_ * (NPTS / 256), 128>>>(pp, spp);

    // #5: interpolation -> g_BP1 rows 64..191
    interp_kernel<<<MTOT / 32, 256>>>();

    // #6: GEMM1 -> packed raw fp16 h1 + BN1 partials
    {
        dim3 grid(GRIDX, C2 / 128);
        gemm1_kernel<<<grid, 256>>>();
    }
    bn_reduce_kernel<<<C2, 256>>>(g1, be1, 1);

    // #8: GEMM2 (BN1+ReLU fused on fragments) -> h2 + BN2 partials
    gemm2_kernel<<<GRIDX, 256>>>();
    bn_reduce_kernel<<<C3, 256>>>(g2, be2, 2);

    // #10: BN2 apply + ReLU + transpose to [B,128,N]
    bn_out_kernel<<<(C3 * MTOT / 4) / 256, 256>>>(out);
}

// round 17
// speedup vs baseline: 1.1681x; 1.1681x over previous
#include <cuda_runtime.h>
#include <cuda_fp16.h>
#include <float.h>
#include <math.h>
#include <stdint.h>

// Problem constants
#define B_    8
#define NPTS  8192
#define NS    2048
#define D1    128
#define D2    256
#define C1    384      // D1 + D2
#define C2    256
#define C3    128
#define MTOT  (B_ * NPTS)   // 65536
#define GRIDX (MTOT / 128)  // 512 column blocks per GEMM

// ---------------------------------------------------------------------------
// Scratch (static device globals — no allocations allowed)
// ---------------------------------------------------------------------------
__device__ __align__(16) uint32_t g_BP1[(size_t)(C1 / 2) * MTOT]; // 48 MB GEMM1 B (packed fp16 k-pairs)
__device__ __align__(16) uint32_t g_BP2[(size_t)(C2 / 2) * MTOT]; // 32 MB h1 RAW packed fp16 k-pairs
__device__ float  g_h2[(size_t)C3 * MTOT];       // 32 MB GEMM2 out (pre-BN) [c][m]
__device__ float  g_sfT[(size_t)B_ * NS * D2];   // 16 MB sfeat transposed [b][s][c]
__device__ float4 g_w[MTOT];                     // per-point 3-NN weights
__device__ int4   g_i[MTOT];                     // per-point 3-NN indices
__device__ float2 g_ss1[C2];                     // BN1 (scale, shift) fp32
__device__ float2 g_ss2[C3];                     // BN2 (scale, shift)
__device__ __align__(4) __half g_sc1h[C2];       // BN1 scale, fp16 (fragment fuse)
__device__ __align__(4) __half g_sh1h[C2];       // BN1 shift, fp16
__device__ __align__(16) __half g_W1h[C2 * C1];  // fp16 weights, row-major
__device__ __align__(16) __half g_W2h[C3 * C2];
// per-block BN partials (deterministic reduction, no atomics)
__device__ float g_psA[C2 * GRIDX], g_pqA[C2 * GRIDX];
__device__ float g_psB[C3 * GRIDX], g_pqB[C3 * GRIDX];

__device__ __forceinline__ void mma16816(float* d, const uint32_t* a, const uint32_t* b) {
    asm volatile(
        "mma.sync.aligned.m16n8k16.row.col.f32.f16.f16.f32 "
        "{%0,%1,%2,%3}, {%4,%5,%6,%7}, {%8,%9}, {%0,%1,%2,%3};\n"
        : "+f"(d[0]), "+f"(d[1]), "+f"(d[2]), "+f"(d[3])
        : "r"(a[0]), "r"(a[1]), "r"(a[2]), "r"(a[3]), "r"(b[0]), "r"(b[1]));
}

__device__ __forceinline__ void cp_async16(uint32_t smem_addr, const void* gptr) {
    asm volatile("cp.async.ca.shared.global [%0], [%1], 16;\n"
                 :: "r"(smem_addr), "l"(gptr));
}
#define CP_COMMIT()  asm volatile("cp.async.commit_group;\n")
#define CP_WAIT(N)   asm volatile("cp.async.wait_group %0;\n" :: "n"(N))

// ---------------------------------------------------------------------------
// Kernel 1 (launch #1): fused prep — weights->fp16, skip pack, sfeat transpose
// ---------------------------------------------------------------------------
#define PREP_W_BLOCKS   384
#define PREP_PS_BLOCKS  4096
#define PREP_TR_BLOCKS  4096
#define PREP_TOTAL      (PREP_W_BLOCKS + PREP_PS_BLOCKS + PREP_TR_BLOCKS)

__global__ void __launch_bounds__(256) prep_all_kernel(
    const float* __restrict__ W1, const float* __restrict__ W2,
    const float* __restrict__ skip, const float* __restrict__ sfeat)
{
    const int bid = blockIdx.x;
    const int tid = threadIdx.x;

    if (bid < PREP_W_BLOCKS) {
        int i = bid * 256 + tid;
        if (i < C2 * C1) g_W1h[i] = __float2half_rn(W1[i]);
        if (i < C3 * C2) g_W2h[i] = __float2half_rn(W2[i]);
        return;
    }
    if (bid < PREP_W_BLOCKS + PREP_PS_BLOCKS) {
        int pb = bid - PREP_W_BLOCKS;
        int cp = pb >> 6;
        int m0 = ((pb & 63) * 256 + tid) * 4;
        int b  = m0 / NPTS;
        int n  = m0 % NPTS;
        const float* r0 = skip + ((size_t)b * D1 + 2 * cp)     * NPTS + n;
        const float* r1 = skip + ((size_t)b * D1 + 2 * cp + 1) * NPTS + n;
        float4 v0 = *(const float4*)r0;
        float4 v1 = *(const float4*)r1;
        uint32_t p[4];
        const float* x0 = &v0.x; const float* x1 = &v1.x;
        #pragma unroll
        for (int e = 0; e < 4; e++) {
            __half2 h = __floats2half2_rn(x0[e], x1[e]);
            p[e] = *reinterpret_cast<uint32_t*>(&h);
        }
        *(uint4*)&g_BP1[(size_t)cp * MTOT + m0] = *(uint4*)p;
        return;
    }
    {
        __shared__ float tile[32][33];
        int tb = bid - PREP_W_BLOCKS - PREP_PS_BLOCKS;
        int s0 = (tb & 63) * 32;
        int c0 = ((tb >> 6) & 7) * 32;
        int b  = tb >> 9;
        int tx = tid & 31;
        int ty = tid >> 5;

        #pragma unroll
        for (int r = 0; r < 32; r += 8)
            tile[ty + r][tx] = sfeat[((size_t)b * D2 + c0 + ty + r) * NS + s0 + tx];
        __syncthreads();
        #pragma unroll
        for (int r = 0; r < 32; r += 8)
            g_sfT[((size_t)b * NS + s0 + ty + r) * D2 + c0 + tx] = tile[tx][ty + r];
    }
}

// ---------------------------------------------------------------------------
// Kernel 2 (launch #2): 3-NN search — OCCUPANCY FIX: 1 pt/thread, 512 blocks
//   (3.5 blocks/SM instead of 1.7 -> 2x warps/SMSP to hide LDS+FMA latency).
// ---------------------------------------------------------------------------
__global__ void __launch_bounds__(128) knn_kernel(
    const float* __restrict__ pp, const float* __restrict__ spp)
{
    __shared__ float4 ssmp[NS];       // 32 KB

    const int b   = blockIdx.x >> 6;           // 64 blocks per batch
    const int n0  = (blockIdx.x & 63) << 7;    // 128 points per block
    const int tid = threadIdx.x;

    const float* sb = spp + (size_t)b * 3 * NS;
    for (int s = tid; s < NS; s += 128) {
        float x = sb[s], y = sb[s + NS], z = sb[s + 2 * NS];
        ssmp[s] = make_float4(x, y, z, fmaf(x, x, fmaf(y, y, z * z)));
    }
    __syncthreads();

    const int n = n0 + tid;
    const float* pb = pp + (size_t)b * 3 * NPTS;
    const float px = pb[n], py = pb[n + NPTS], pz = pb[n + 2 * NPTS];

    float d0 = FLT_MAX, d1 = FLT_MAX, d2 = FLT_MAX;
    int   i0 = 0, i1 = 0, i2 = 0;

    #pragma unroll 8
    for (int j = 0; j < NS; j++) {
        float4 q   = ssmp[j];
        float  sc  = fmaf(-2.0f, fmaf(px, q.x, fmaf(py, q.y, pz * q.z)), q.w);
        if (sc < d2) {
            if (sc < d1) {
                d2 = d1; i2 = i1;
                if (sc < d0) { d1 = d0; i1 = i0; d0 = sc; i0 = j; }
                else         { d1 = sc; i1 = j; }
            } else { d2 = sc; i2 = j; }
        }
    }

    const float p2 = fmaf(px, px, fmaf(py, py, pz * pz));
    float a0 = 1.0f / ((d0 + p2) + 1e-8f);
    float a1 = 1.0f / ((d1 + p2) + 1e-8f);
    float a2 = 1.0f / ((d2 + p2) + 1e-8f);
    const float inv = 1.0f / (a0 + a1 + a2);

    g_w[b * NPTS + n] = make_float4(a0 * inv, a1 * inv, a2 * inv, 0.0f);
    g_i[b * NPTS + n] = make_int4(i0, i1, i2, 0);
}

// ---------------------------------------------------------------------------
// Kernel 3 (launch #3): interpolation -> g_BP1 rows 64..191 (half2 packed)
// ---------------------------------------------------------------------------
__global__ void __launch_bounds__(256) interp_kernel()
{
    __shared__ float  st[D2][33];
    __shared__ float4 sw[32];
    __shared__ int4   si[32];

    const int m0  = blockIdx.x * 32;
    const int b   = m0 / NPTS;
    const int tid = threadIdx.x;

    if (tid < 32) { sw[tid] = g_w[m0 + tid]; si[tid] = g_i[m0 + tid]; }
    __syncthreads();

    const float* fT = g_sfT + (size_t)b * NS * D2;
    #pragma unroll 8
    for (int p = 0; p < 32; p++) {
        float4 w = sw[p];
        int4   ii = si[p];
        float v = fmaf(w.x, __ldg(fT + (size_t)ii.x * D2 + tid),
                  fmaf(w.y, __ldg(fT + (size_t)ii.y * D2 + tid),
                       w.z * __ldg(fT + (size_t)ii.z * D2 + tid)));
        st[tid][p] = v;
    }
    __syncthreads();

    const int cpb = tid >> 3;
    const int j   = (tid & 7) << 2;
    #pragma unroll
    for (int r = 0; r < 4; r++) {
        int cp = r * 32 + cpb;
        uint32_t v[4];
        #pragma unroll
        for (int e = 0; e < 4; e++) {
            __half2 h = __floats2half2_rn(st[2 * cp][j + e], st[2 * cp + 1][j + e]);
            v[e] = *reinterpret_cast<uint32_t*>(&h);
        }
        *(uint4*)&g_BP1[(size_t)(64 + cp) * MTOT + m0 + j] = *(uint4*)v;
    }
}

// ---------------------------------------------------------------------------
// Shared MMA compute (As [m][kpair], Bs [kpair][n ^ (kp<<3)])
// ---------------------------------------------------------------------------
#define MMA_COMPUTE(ASBUF, BSBUF)                                             \
{                                                                             \
    uint32_t bf[4][2];                                                        \
    _Pragma("unroll")                                                         \
    for (int nt = 0; nt < 4; nt++) {                                          \
        int n = wn * 32 + nt * 8 + g;                                         \
        bf[nt][0] = (BSBUF)[t * 128 + (n ^ (t << 3))];                        \
        bf[nt][1] = (BSBUF)[(t + 4) * 128 + (n ^ ((t + 4) << 3))];            \
    }                                                                         \
    _Pragma("unroll")                                                         \
    for (int mt = 0; mt < 4; mt++) {                                          \
        int r = wm * 64 + mt * 16 + g;                                        \
        uint32_t ah[4];                                                       \
        ah[0] = (ASBUF)[r * 8 + t];                                           \
        ah[1] = (ASBUF)[(r + 8) * 8 + t];                                     \
        ah[2] = (ASBUF)[r * 8 + t + 4];                                       \
        ah[3] = (ASBUF)[(r + 8) * 8 + t + 4];                                 \
        _Pragma("unroll")                                                     \
        for (int nt = 0; nt < 4; nt++)                                        \
            mma16816(acc[mt][nt], ah, bf[nt]);                                \
    }                                                                         \
}

// gemm2 variant: BN1 + ReLU applied on B fragments (half2 hfma2/hmax2)
#define MMA_COMPUTE_BN(ASBUF, BSBUF, KI)                                      \
{                                                                             \
    const __half2 z2 = __float2half2_rn(0.0f);                                \
    __half2 sc0 = ((const __half2*)g_sc1h)[(KI) * 8 + t];                     \
    __half2 sh0 = ((const __half2*)g_sh1h)[(KI) * 8 + t];                     \
    __half2 sc1 = ((const __half2*)g_sc1h)[(KI) * 8 + t + 4];                 \
    __half2 sh1 = ((const __half2*)g_sh1h)[(KI) * 8 + t + 4];                 \
    uint32_t bf[4][2];                                                        \
    _Pragma("unroll")                                                         \
    for (int nt = 0; nt < 4; nt++) {                                          \
        int n = wn * 32 + nt * 8 + g;                                         \
        bf[nt][0] = (BSBUF)[t * 128 + (n ^ (t << 3))];                        \
        bf[nt][1] = (BSBUF)[(t + 4) * 128 + (n ^ ((t + 4) << 3))];            \
        __half2 h0 = *reinterpret_cast<__half2*>(&bf[nt][0]);                 \
        __half2 h1 = *reinterpret_cast<__half2*>(&bf[nt][1]);                 \
        h0 = __hmax2(__hfma2(h0, sc0, sh0), z2);                              \
        h1 = __hmax2(__hfma2(h1, sc1, sh1), z2);                              \
        bf[nt][0] = *reinterpret_cast<uint32_t*>(&h0);                        \
        bf[nt][1] = *reinterpret_cast<uint32_t*>(&h1);                        \
    }                                                                         \
    _Pragma("unroll")                                                         \
    for (int mt = 0; mt < 4; mt++) {                                          \
        int r = wm * 64 + mt * 16 + g;                                        \
        uint32_t ah[4];                                                       \
        ah[0] = (ASBUF)[r * 8 + t];                                           \
        ah[1] = (ASBUF)[(r + 8) * 8 + t];                                     \
        ah[2] = (ASBUF)[r * 8 + t + 4];                                       \
        ah[3] = (ASBUF)[(r + 8) * 8 + t + 4];                                 \
        _Pragma("unroll")                                                     \
        for (int nt = 0; nt < 4; nt++)                                        \
            mma16816(acc[mt][nt], ah, bf[nt]);                                \
    }                                                                         \
}

// BN partial-stat emission (sum/sumsq from fp32 accumulators)
#define BN_PARTIALS(PSUM, PSQ, SS_SMEM, SQ_SMEM)                              \
{                                                                             \
    __syncthreads();                                                          \
    float* Ssum = (SS_SMEM);                                                  \
    float* Ssq  = (SQ_SMEM);                                                  \
    const int ci = wn * 4 + t;                                                \
    _Pragma("unroll")                                                         \
    for (int mt = 0; mt < 4; mt++) {                                          \
        int r0 = wm * 64 + mt * 16 + g;                                       \
        float s0 = 0.f, q0 = 0.f, s1 = 0.f, q1 = 0.f;                         \
        _Pragma("unroll")                                                     \
        for (int nt = 0; nt < 4; nt++) {                                      \
            float e0 = acc[mt][nt][0], e1 = acc[mt][nt][1];                   \
            float e2 = acc[mt][nt][2], e3 = acc[mt][nt][3];                   \
            s0 += e0 + e1;  q0 += e0 * e0 + e1 * e1;                          \
            s1 += e2 + e3;  q1 += e2 * e2 + e3 * e3;                          \
        }                                                                     \
        Ssum[ci * 128 + r0]     = s0;  Ssq[ci * 128 + r0]     = q0;           \
        Ssum[ci * 128 + r0 + 8] = s1;  Ssq[ci * 128 + r0 + 8] = q1;           \
    }                                                                         \
    __syncthreads();                                                          \
    if (tid < 128) {                                                          \
        float s = 0.f;                                                        \
        _Pragma("unroll")                                                     \
        for (int c = 0; c < 16; c++) s += Ssum[c * 128 + tid];                \
        (PSUM)[(size_t)(i0 + tid) * GRIDX + blockIdx.x] = s;                  \
    } else {                                                                  \
        int r = tid - 128;                                                    \
        float q = 0.f;                                                        \
        _Pragma("unroll")                                                     \
        for (int c = 0; c < 16; c++) q += Ssq[c * 128 + r];                   \
        (PSQ)[(size_t)(i0 + r) * GRIDX + blockIdx.x] = q;                     \
    }                                                                         \
}

// ---------------------------------------------------------------------------
// Kernel 4 (launch #4 — PROFILED sentinel): GEMM1 (measured 70us stable).
//   Epilogue packs h1 as raw fp16 k-pairs into g_BP2 + BN1 partials.
// ---------------------------------------------------------------------------
__global__ void __launch_bounds__(256) gemm1_kernel()
{
    __shared__ uint32_t As[4][128 * 8];
    __shared__ uint32_t Bs[4][8 * 128];

    const int tid  = threadIdx.x;
    const int lane = tid & 31;
    const int wid  = tid >> 5;
    const int wm   = wid >> 2;
    const int wn   = wid & 3;
    const int g    = lane >> 2;
    const int t    = lane & 3;

    const int j0 = blockIdx.x * 128;
    const int i0 = blockIdx.y * 128;

    const int arow = tid >> 1;
    const int akh  = tid & 1;
    const int brp  = tid >> 5;
    const int bc0  = lane * 4;

    const uint32_t a_dst0 = (uint32_t)__cvta_generic_to_shared(&As[0][arow * 8 + akh * 4]);
    const uint32_t b_dst0 = (uint32_t)__cvta_generic_to_shared(&Bs[0][brp * 128 + (bc0 ^ (brp << 3))]);
    const __half*   a_src0 = g_W1h + (size_t)(i0 + arow) * C1 + akh * 8;
    const uint32_t* b_src0 = g_BP1 + (size_t)brp * MTOT + j0 + bc0;

    float acc[4][4][4];
    #pragma unroll
    for (int mt = 0; mt < 4; mt++)
        #pragma unroll
        for (int nt = 0; nt < 4; nt++)
            #pragma unroll
            for (int e = 0; e < 4; e++) acc[mt][nt][e] = 0.0f;

    #define G1_ISSUE(step)                                                    \
    {                                                                         \
        int s_ = (step) & 3;                                                  \
        cp_async16(a_dst0 + s_ * 4096, a_src0 + (step) * 16);                 \
        cp_async16(b_dst0 + s_ * 4096, b_src0 + (size_t)(step) * 8 * MTOT);   \
        CP_COMMIT();                                                          \
    }

    G1_ISSUE(0); G1_ISSUE(1); G1_ISSUE(2);

    #pragma unroll 1
    for (int i = 0; i < 21; i++) {
        CP_WAIT(2);
        __syncthreads();
        G1_ISSUE(i + 3);
        MMA_COMPUTE(As[i & 3], Bs[i & 3]);
    }
    CP_WAIT(2); __syncthreads(); MMA_COMPUTE(As[21 & 3], Bs[21 & 3]);
    CP_WAIT(1); __syncthreads(); MMA_COMPUTE(As[22 & 3], Bs[22 & 3]);
    CP_WAIT(0); __syncthreads(); MMA_COMPUTE(As[23 & 3], Bs[23 & 3]);

    // ---- epilogue: pack h1 -> raw fp16 k-pairs in g_BP2 ----
    #pragma unroll
    for (int mt = 0; mt < 4; mt++) {
        #pragma unroll
        for (int nt = 0; nt < 4; nt++) {
            float v0 = acc[mt][nt][0], v1 = acc[mt][nt][1];
            float v2 = acc[mt][nt][2], v3 = acc[mt][nt][3];
            float p0 = __shfl_down_sync(0xFFFFFFFFu, v0, 4);
            float p1 = __shfl_down_sync(0xFFFFFFFFu, v1, 4);
            float p2 = __shfl_down_sync(0xFFFFFFFFu, v2, 4);
            float p3 = __shfl_down_sync(0xFFFFFFFFu, v3, 4);
            if (!(g & 1)) {
                int r   = wm * 64 + mt * 16 + g;
                int cp0 = (i0 + r) >> 1;
                int col = j0 + wn * 32 + nt * 8 + 2 * t;
                __half2 h0 = __floats2half2_rn(v0, p0);
                __half2 h1 = __floats2half2_rn(v1, p1);
                uint2 w0 = make_uint2(*(uint32_t*)&h0, *(uint32_t*)&h1);
                *(uint2*)&g_BP2[(size_t)cp0 * MTOT + col] = w0;
                __half2 h2 = __floats2half2_rn(v2, p2);
                __half2 h3 = __floats2half2_rn(v3, p3);
                uint2 w1 = make_uint2(*(uint32_t*)&h2, *(uint32_t*)&h3);
                *(uint2*)&g_BP2[(size_t)(cp0 + 4) * MTOT + col] = w1;
            }
        }
    }

    BN_PARTIALS(g_psA, g_pqA, (float*)As, (float*)Bs);
    #undef G1_ISSUE
}

// ---------------------------------------------------------------------------
// Kernel 5: GEMM2 — pure-copy cp.async loaders; BN1+ReLU fused on B FRAGMENTS.
// ---------------------------------------------------------------------------
__global__ void __launch_bounds__(256) gemm2_kernel()
{
    __shared__ uint32_t As[4][128 * 8];
    __shared__ uint32_t Bs[4][8 * 128];

    const int tid  = threadIdx.x;
    const int lane = tid & 31;
    const int wid  = tid >> 5;
    const int wm   = wid >> 2;
    const int wn   = wid & 3;
    const int g    = lane >> 2;
    const int t    = lane & 3;

    const int j0 = blockIdx.x * 128;
    const int i0 = 0;

    const int arow = tid >> 1;
    const int akh  = tid & 1;
    const int brp  = tid >> 5;
    const int bc0  = lane * 4;

    const uint32_t a_dst0 = (uint32_t)__cvta_generic_to_shared(&As[0][arow * 8 + akh * 4]);
    const uint32_t b_dst0 = (uint32_t)__cvta_generic_to_shared(&Bs[0][brp * 128 + (bc0 ^ (brp << 3))]);
    const __half*   a_src0 = g_W2h + (size_t)arow * C2 + akh * 8;
    const uint32_t* b_src0 = g_BP2 + (size_t)brp * MTOT + j0 + bc0;

    float acc[4][4][4];
    #pragma unroll
    for (int mt = 0; mt < 4; mt++)
        #pragma unroll
        for (int nt = 0; nt < 4; nt++)
            #pragma unroll
            for (int e = 0; e < 4; e++) acc[mt][nt][e] = 0.0f;

    #define G2_ISSUE(step)                                                    \
    {                                                                         \
        int s_ = (step) & 3;                                                  \
        cp_async16(a_dst0 + s_ * 4096, a_src0 + (step) * 16);                 \
        cp_async16(b_dst0 + s_ * 4096, b_src0 + (size_t)(step) * 8 * MTOT);   \
        CP_COMMIT();                                                          \
    }

    G2_ISSUE(0); G2_ISSUE(1); G2_ISSUE(2);

    #pragma unroll 1
    for (int i = 0; i < 13; i++) {
        CP_WAIT(2);
        __syncthreads();
        G2_ISSUE(i + 3);
        MMA_COMPUTE_BN(As[i & 3], Bs[i & 3], i);
    }
    CP_WAIT(2); __syncthreads(); MMA_COMPUTE_BN(As[13 & 3], Bs[13 & 3], 13);
    CP_WAIT(1); __syncthreads(); MMA_COMPUTE_BN(As[14 & 3], Bs[14 & 3], 14);
    CP_WAIT(0); __syncthreads(); MMA_COMPUTE_BN(As[15 & 3], Bs[15 & 3], 15);

    // store h2 fp32 + BN2 partials
    #pragma unroll
    for (int mt = 0; mt < 4; mt++) {
        #pragma unroll
        for (int nt = 0; nt < 4; nt++) {
            int row = wm * 64 + mt * 16 + g;
            int col = j0 + wn * 32 + nt * 8 + 2 * t;
            *(float2*)&g_h2[(size_t)row * MTOT + col] =
                make_float2(acc[mt][nt][0], acc[mt][nt][1]);
            *(float2*)&g_h2[(size_t)(row + 8) * MTOT + col] =
                make_float2(acc[mt][nt][2], acc[mt][nt][3]);
        }
    }

    BN_PARTIALS(g_psB, g_pqB, (float*)As, (float*)Bs);
    #undef G2_ISSUE
}

// ---------------------------------------------------------------------------
// Kernel 6: reduce per-block partials -> per-channel (scale, shift)
// ---------------------------------------------------------------------------
__global__ void __launch_bounds__(256) bn_reduce_kernel(
    const float* __restrict__ g, const float* __restrict__ beta, int which)
{
    const int c   = blockIdx.x;
    const int tid = threadIdx.x;
    const float* ps = (which == 1) ? g_psA : g_psB;
    const float* pq = (which == 1) ? g_pqA : g_pqB;

    double s = (double)ps[(size_t)c * GRIDX + tid] + (double)ps[(size_t)c * GRIDX + tid + 256];
    double q = (double)pq[(size_t)c * GRIDX + tid] + (double)pq[(size_t)c * GRIDX + tid + 256];

    __shared__ double r1[256], r2[256];
    r1[tid] = s;  r2[tid] = q;
    __syncthreads();
    for (int o = 128; o > 0; o >>= 1) {
        if (tid < o) { r1[tid] += r1[tid + o]; r2[tid] += r2[tid + o]; }
        __syncthreads();
    }
    if (tid == 0) {
        double mean = r1[0] / (double)MTOT;
        double var  = r2[0] / (double)MTOT - mean * mean;
        double rs   = 1.0 / sqrt(var + 1e-5);
        float scale = (float)((double)g[c] * rs);
        float shift = (float)((double)beta[c] - mean * (double)g[c] * rs);
        if (which == 1) {
            g_ss1[c]  = make_float2(scale, shift);
            g_sc1h[c] = __float2half_rn(scale);
            g_sh1h[c] = __float2half_rn(shift);
        } else {
            g_ss2[c] = make_float2(scale, shift);
        }
    }
}

// ---------------------------------------------------------------------------
// Kernel 7: final BN2 + ReLU + layout transform [c][b*N+n] -> [b][c][n]
// ---------------------------------------------------------------------------
__global__ void __launch_bounds__(256) bn_out_kernel(float* __restrict__ out)
{
    size_t f = (size_t)blockIdx.x * blockDim.x + threadIdx.x;
    size_t e = f * 4;
    int c = (int)(e / MTOT);
    int m = (int)(e % MTOT);
    int b = m / NPTS;
    int n = m % NPTS;

    float4 v = ((const float4*)g_h2)[f];
    float2 ss = g_ss2[c];
    v.x = fmaxf(fmaf(v.x, ss.x, ss.y), 0.0f);
    v.y = fmaxf(fmaf(v.y, ss.x, ss.y), 0.0f);
    v.z = fmaxf(fmaf(v.z, ss.x, ss.y), 0.0f);
    v.w = fmaxf(fmaf(v.w, ss.x, ss.y), 0.0f);
    *(float4*)(out + ((size_t)b * C3 + c) * NPTS + n) = v;
}

// ---------------------------------------------------------------------------
// Launcher — prep re-fused; gemm1 back in the profiled #4 sentinel slot
// ---------------------------------------------------------------------------
extern "C" void kernel_launch(void* const* d_in, const int* in_sizes, int n_in,
                              void* d_out, int out_size)
{
    const float* pp    = (const float*)d_in[0];
    const float* spp   = (const float*)d_in[1];
    const float* skip  = (const float*)d_in[2];
    const float* sfeat = (const float*)d_in[3];
    const float* W1    = (const float*)d_in[4];
    // d_in[5] = b1 (cancels inside BN)
    const float* g1    = (const float*)d_in[6];
    const float* be1   = (const float*)d_in[7];
    const float* W2    = (const float*)d_in[8];
    // d_in[9] = b2 (cancels inside BN)
    const float* g2    = (const float*)d_in[10];
    const float* be2   = (const float*)d_in[11];
    float* out = (float*)d_out;

    // #1: fused preprocessing
    prep_all_kernel<<<PREP_TOTAL, 256>>>(W1, W2, skip, sfeat);

    // #2: 3-NN — 512 blocks, 1 pt/thread (occupancy fix)
    knn_kernel<<<B_ * (NPTS / 128), 128>>>(pp, spp);

    // #3: interpolation -> g_BP1 rows 64..191
    interp_kernel<<<MTOT / 32, 256>>>();

    // #4 (PROFILED sentinel): GEMM1 -> packed raw fp16 h1 + BN1 partials
    {
        dim3 grid(GRIDX, C2 / 128);
        gemm1_kernel<<<grid, 256>>>();
    }
    bn_reduce_kernel<<<C2, 256>>>(g1, be1, 1);

    // #6: GEMM2 (BN1+ReLU fused on fragments) -> h2 + BN2 partials
    gemm2_kernel<<<GRIDX, 256>>>();
    bn_reduce_kernel<<<C3, 256>>>(g2, be2, 2);

    // #8: BN2 apply + ReLU + transpose to [B,128,N]
    bn_out_kernel<<<(C3 * MTOT / 4) / 256, 256>>>(out);
}